// round 15
// baseline (speedup 1.0000x reference)
#include <cuda_runtime.h>
#include <math.h>
#include <stdint.h>

// Problem constants
#define EDIM 384
#define GDIM 256
#define HNUM 6
#define DHH  64
#define OUTD 256
#define HE   (HNUM*EDIM)   // 2304
#define UNIT 128
#define SLOTS 8            // MAX_N 1024 / UNIT
#define NUNITS (GDIM*SLOTS)
#define TILE 32
#define XPITCH 97                      // float4 pitch per node (conflict-free)
#define XBUF_F4 (TILE*XPITCH)          // 3104 float4 per buffer
#define SMEM_X (2*XBUF_F4*16)          // 99328 B double buffer

// ---------------- device scratch ----------------
__device__ __align__(16) float g_wk[HNUM*EDIM];
__device__ __align__(16) float g_Wc[OUTD*EDIM];      // Wp @ Wo
__device__ __align__(16) float g_cb[OUTD];           // Wp.bo + bp
__device__            int   g_off[GDIM + 1];
__device__ __align__(16) float g_accx[GDIM*HE];      // attn-weighted x sums (atomic)
__device__ __align__(16) float g_pooled[GDIM*EDIM];  // pooled incl. bv
__device__ __align__(16) float g_usum[NUNITS*HNUM];  // per-unit exp sums

// ---------------- helpers ----------------
__device__ __forceinline__ float warp_sum(float v) {
#pragma unroll
    for (int s = 16; s > 0; s >>= 1) v += __shfl_xor_sync(0xffffffffu, v, s);
    return v;
}
__device__ __forceinline__ void cp_async16(uint32_t saddr, const void* gaddr) {
    asm volatile("cp.async.cg.shared.global [%0], [%1], 16;" :: "r"(saddr), "l"(gaddr));
}
__device__ __forceinline__ void cp_commit() {
    asm volatile("cp.async.commit_group;");
}
__device__ __forceinline__ void cp_wait1() {
    asm volatile("cp.async.wait_group 1;");
}

// ---------------- prep: wkq (blocks 0..5) + scan (6) + cb (7..28) ----------
__global__ void __launch_bounds__(EDIM)
prep_kernel(const float* __restrict__ Wq, const float* __restrict__ query,
            const float* __restrict__ bq, const float* __restrict__ Wk,
            const int* __restrict__ sizes, const float* __restrict__ Wp,
            const float* __restrict__ bo, const float* __restrict__ bp) {
    int b = blockIdx.x;
    int tid = threadIdx.x;
    int warp = tid >> 5;
    int lane = tid & 31;
    if (b < HNUM) {
        int h = b;
        __shared__ float qs[DHH];
        for (int d = warp; d < DHH; d += 12) {
            int row = h * DHH + d;
            float s = 0.f;
            for (int j = lane; j < EDIM; j += 32) s += Wq[(size_t)row * EDIM + j] * query[j];
            s = warp_sum(s);
            if (lane == 0) qs[d] = (s + bq[row]) * 0.125f;
        }
        __syncthreads();
        float s = 0.f;
#pragma unroll 8
        for (int d = 0; d < DHH; d++)
            s += qs[d] * Wk[(size_t)(h * DHH + d) * EDIM + tid];
        g_wk[h * EDIM + tid] = s;
    } else if (b == HNUM) {
        __shared__ int s[GDIM];
        if (tid < GDIM) s[tid] = sizes[tid];
        __syncthreads();
        for (int d = 1; d < GDIM; d <<= 1) {
            int add = (tid < GDIM && tid >= d) ? s[tid - d] : 0;
            __syncthreads();
            if (tid < GDIM) s[tid] += add;
            __syncthreads();
        }
        if (tid < GDIM) {
            g_off[tid] = s[tid] - sizes[tid];
            if (tid == GDIM - 1) g_off[GDIM] = s[tid];
        }
    } else {
        int gw = (b - HNUM - 1) * 12 + warp;
        if (gw < OUTD) {
            float s = 0.f;
            for (int j = lane; j < EDIM; j += 32) s += Wp[(size_t)gw * EDIM + j] * bo[j];
            s = warp_sum(s);
            if (lane == 0) g_cb[gw] = s + bp[gw];
        }
    }
}

// ---------------- 64x32-tiled fp32 GEMM, 4x4 microtile, 128 threads ------
template <bool TB, bool BIAS>
__global__ void __launch_bounds__(128)
gemm_s(const float* __restrict__ A, int lda,
       const float* __restrict__ B, int ldb,
       float* __restrict__ C, int ldc,
       const float* __restrict__ bias,
       int M, int N, int K,
       int zA, int zB, int zC, int zBias) {
    A += (size_t)blockIdx.z * zA;
    B += (size_t)blockIdx.z * zB;
    C += (size_t)blockIdx.z * zC;
    if (BIAS) bias += (size_t)blockIdx.z * zBias;

    __shared__ float As[32][68];
    __shared__ float Bs[32][36];
    int tid = threadIdx.x;
    int bm = blockIdx.y * 64, bn = blockIdx.x * 32;
    int tx = tid & 7, ty = tid >> 3;

    float acc[4][4];
#pragma unroll
    for (int i = 0; i < 4; i++)
#pragma unroll
        for (int j = 0; j < 4; j++) acc[i][j] = 0.f;

    for (int k0 = 0; k0 < K; k0 += 32) {
        {
            int kk = tid & 31, mb = tid >> 5;
#pragma unroll
            for (int i = 0; i < 16; i++) {
                int mm = mb + i * 4;
                As[kk][mm] = A[(size_t)(bm + mm) * lda + k0 + kk];
            }
        }
        if (TB) {
            int kk = tid & 31, nb = tid >> 5;
#pragma unroll
            for (int i = 0; i < 8; i++) {
                int nn = nb + i * 4;
                Bs[kk][nn] = B[(size_t)(bn + nn) * ldb + k0 + kk];
            }
        } else {
            int nn = tid & 31, kb = tid >> 5;
#pragma unroll
            for (int i = 0; i < 8; i++) {
                int k2 = kb + i * 4;
                Bs[k2][nn] = B[(size_t)(k0 + k2) * ldb + bn + nn];
            }
        }
        __syncthreads();
#pragma unroll
        for (int kk = 0; kk < 32; kk++) {
            float4 a = *(const float4*)&As[kk][ty * 4];
            float4 bb = *(const float4*)&Bs[kk][tx * 4];
            acc[0][0] = fmaf(a.x, bb.x, acc[0][0]); acc[0][1] = fmaf(a.x, bb.y, acc[0][1]);
            acc[0][2] = fmaf(a.x, bb.z, acc[0][2]); acc[0][3] = fmaf(a.x, bb.w, acc[0][3]);
            acc[1][0] = fmaf(a.y, bb.x, acc[1][0]); acc[1][1] = fmaf(a.y, bb.y, acc[1][1]);
            acc[1][2] = fmaf(a.y, bb.z, acc[1][2]); acc[1][3] = fmaf(a.y, bb.w, acc[1][3]);
            acc[2][0] = fmaf(a.z, bb.x, acc[2][0]); acc[2][1] = fmaf(a.z, bb.y, acc[2][1]);
            acc[2][2] = fmaf(a.z, bb.z, acc[2][2]); acc[2][3] = fmaf(a.z, bb.w, acc[2][3]);
            acc[3][0] = fmaf(a.w, bb.x, acc[3][0]); acc[3][1] = fmaf(a.w, bb.y, acc[3][1]);
            acc[3][2] = fmaf(a.w, bb.z, acc[3][2]); acc[3][3] = fmaf(a.w, bb.w, acc[3][3]);
        }
        __syncthreads();
    }
    float4 bv4 = make_float4(0.f, 0.f, 0.f, 0.f);
    if (BIAS) bv4 = *(const float4*)&bias[bn + tx * 4];
#pragma unroll
    for (int i = 0; i < 4; i++) {
        int gm = bm + ty * 4 + i;
        float4 o = make_float4(acc[i][0] + bv4.x, acc[i][1] + bv4.y,
                               acc[i][2] + bv4.z, acc[i][3] + bv4.w);
        *(float4*)&C[(size_t)gm * ldc + bn + tx * 4] = o;
    }
}

// ---------------- fused attention unit: single pass, max-free softmax ------
// block = unit (128 nodes), 256 threads (8 warps). Tiles of 32 nodes staged
// via cp.async double buffer. Per tile:
//   scores: warp w holds wk for k-slice [48w,48w+48) in 72 regs, lane = node,
//           zero shuffles -> partials to smem
//   reduce: 256 threads sum 8 partials, exp, -> s_sc
//   accum:  warp w owns cols [48w,48w+48), reads x tile from SMEM
// Unnormalized sums atomically added to g_accx; per-unit exp sums to g_usum.
extern __shared__ float4 xs4[];   // [2][XBUF_F4]

__global__ void __launch_bounds__(256, 2)
attn2_kernel(const float* __restrict__ x, const int* __restrict__ sizes) {
    __shared__ float part[8][TILE][8];
    __shared__ float s_sc[TILE][8];
    __shared__ float susum[HNUM];

    int u = blockIdx.x;
    int g = u >> 3;
    int slot = u & (SLOTS - 1);
    int size = sizes[g];
    int ustart = slot * UNIT;
    if (ustart >= size) return;
    int ucnt = min(UNIT, size - ustart);
    int off = g_off[g] + ustart;
    int nt = (ucnt + TILE - 1) / TILE;

    int tid = threadIdx.x;
    int warp = tid >> 5;
    int lane = tid & 31;

    if (tid < HNUM) susum[tid] = 0.f;

    // this warp's k-slice weights: 6 heads x 12 float4 = 72 regs
    float4 wkr[HNUM][12];
#pragma unroll
    for (int h = 0; h < HNUM; h++)
#pragma unroll
        for (int j = 0; j < 12; j++)
            wkr[h][j] = *(const float4*)&g_wk[h * EDIM + warp * 48 + 4 * j];

    uint32_t sb = (uint32_t)__cvta_generic_to_shared(xs4);

    // cp.async tile issue (node-major, 96 float4 per node, pitch 97)
    auto issue_tile = [&](int tt) {
        int cntt = min(TILE, ucnt - tt * TILE);
        const float4* gx = (const float4*)(x + (size_t)(off + tt * TILE) * EDIM);
        uint32_t dst = sb + (uint32_t)((tt & 1) * XBUF_F4 * 16);
        int total = cntt * 96;
        for (int i = tid; i < total; i += 256) {
            int node = i / 96;
            int j = i - node * 96;
            cp_async16(dst + (uint32_t)(node * XPITCH + j) * 16, gx + node * 96 + j);
        }
    };

    issue_tile(0);
    cp_commit();
    if (nt > 1) issue_tile(1);
    cp_commit();

    float acc1[HNUM], acc2[HNUM];
#pragma unroll
    for (int h = 0; h < HNUM; h++) { acc1[h] = 0.f; acc2[h] = 0.f; }
    int e1 = warp * 48 + lane;
    bool p2 = (lane < 16);

    for (int t = 0; t < nt; t++) {
        int cnt = min(TILE, ucnt - t * TILE);
        const float4* xb = xs4 + (t & 1) * XBUF_F4;

        cp_wait1();          // tile t resident (all except most recent group)
        __syncthreads();

        // ---- scores: lane = node, k-slice in registers ----
        {
            float a0 = 0.f, a1 = 0.f, a2 = 0.f, a3 = 0.f, a4 = 0.f, a5 = 0.f;
            const float4* row = xb + lane * XPITCH + warp * 12;
#pragma unroll
            for (int j = 0; j < 12; j++) {
                float4 xv = row[j];
                a0 = fmaf(wkr[0][j].x, xv.x, a0); a0 = fmaf(wkr[0][j].y, xv.y, a0);
                a0 = fmaf(wkr[0][j].z, xv.z, a0); a0 = fmaf(wkr[0][j].w, xv.w, a0);
                a1 = fmaf(wkr[1][j].x, xv.x, a1); a1 = fmaf(wkr[1][j].y, xv.y, a1);
                a1 = fmaf(wkr[1][j].z, xv.z, a1); a1 = fmaf(wkr[1][j].w, xv.w, a1);
                a2 = fmaf(wkr[2][j].x, xv.x, a2); a2 = fmaf(wkr[2][j].y, xv.y, a2);
                a2 = fmaf(wkr[2][j].z, xv.z, a2); a2 = fmaf(wkr[2][j].w, xv.w, a2);
                a3 = fmaf(wkr[3][j].x, xv.x, a3); a3 = fmaf(wkr[3][j].y, xv.y, a3);
                a3 = fmaf(wkr[3][j].z, xv.z, a3); a3 = fmaf(wkr[3][j].w, xv.w, a3);
                a4 = fmaf(wkr[4][j].x, xv.x, a4); a4 = fmaf(wkr[4][j].y, xv.y, a4);
                a4 = fmaf(wkr[4][j].z, xv.z, a4); a4 = fmaf(wkr[4][j].w, xv.w, a4);
                a5 = fmaf(wkr[5][j].x, xv.x, a5); a5 = fmaf(wkr[5][j].y, xv.y, a5);
                a5 = fmaf(wkr[5][j].z, xv.z, a5); a5 = fmaf(wkr[5][j].w, xv.w, a5);
            }
            *(float4*)&part[warp][lane][0] = make_float4(a0, a1, a2, a3);
            *(float2*)&part[warp][lane][4] = make_float2(a4, a5);
        }
        __syncthreads();

        // ---- reduce partials + exp ----
        {
            int n = tid >> 3, h = tid & 7;
            if (h < HNUM && n < cnt) {
                float s = part[0][n][h] + part[1][n][h] + part[2][n][h] + part[3][n][h]
                        + part[4][n][h] + part[5][n][h] + part[6][n][h] + part[7][n][h];
                float ev = __expf(s);
                s_sc[n][h] = ev;
                atomicAdd(&susum[h], ev);
            }
        }
        __syncthreads();

        // ---- accumulate from smem tile (warp owns 48 columns) ----
        {
            const float* xsf = (const float*)xb;   // pitch 4*XPITCH floats
#pragma unroll 4
            for (int n = 0; n < cnt; n++) {
                float4 a4v = *(const float4*)&s_sc[n][0];
                float2 a2v = *(const float2*)&s_sc[n][4];
                float xv1 = xsf[n * (4 * XPITCH) + e1];
                acc1[0] = fmaf(a4v.x, xv1, acc1[0]);
                acc1[1] = fmaf(a4v.y, xv1, acc1[1]);
                acc1[2] = fmaf(a4v.z, xv1, acc1[2]);
                acc1[3] = fmaf(a4v.w, xv1, acc1[3]);
                acc1[4] = fmaf(a2v.x, xv1, acc1[4]);
                acc1[5] = fmaf(a2v.y, xv1, acc1[5]);
                if (p2) {
                    float xv2 = xsf[n * (4 * XPITCH) + e1 + 32];
                    acc2[0] = fmaf(a4v.x, xv2, acc2[0]);
                    acc2[1] = fmaf(a4v.y, xv2, acc2[1]);
                    acc2[2] = fmaf(a4v.z, xv2, acc2[2]);
                    acc2[3] = fmaf(a4v.w, xv2, acc2[3]);
                    acc2[4] = fmaf(a2v.x, xv2, acc2[4]);
                    acc2[5] = fmaf(a2v.y, xv2, acc2[5]);
                }
            }
        }
        __syncthreads();   // tile buffer free for prefetch

        if (t + 2 < nt) issue_tile(t + 2);
        cp_commit();
    }

    // flush unnormalized sums
    {
        float* dst = &g_accx[(size_t)g * HE + e1];
#pragma unroll
        for (int h = 0; h < HNUM; h++) atomicAdd(dst + h * EDIM, acc1[h]);
        if (p2) {
#pragma unroll
            for (int h = 0; h < HNUM; h++) atomicAdd(dst + h * EDIM + 32, acc2[h]);
        }
    }
    if (tid < HNUM) g_usum[u * HNUM + tid] = susum[tid];
}

// ---------------- normalize accx by per-group exp sums ----------------
__global__ void __launch_bounds__(EDIM)
norm_kernel(const int* __restrict__ sizes) {
    __shared__ float s_inv[HNUM];
    int g = blockIdx.x;
    int tid = threadIdx.x;
    int nslots = (sizes[g] + UNIT - 1) / UNIT;
    if (tid < HNUM) {
        float d = 0.f;
        for (int s = 0; s < nslots; s++) d += g_usum[(g * SLOTS + s) * HNUM + tid];
        s_inv[tid] = 1.f / d;
    }
    __syncthreads();
#pragma unroll
    for (int h = 0; h < HNUM; h++)
        g_accx[(size_t)g * HE + h * EDIM + tid] *= s_inv[h];
}

// ---------------- launch ----------------
extern "C" void kernel_launch(void* const* d_in, const int* in_sizes, int n_in,
                              void* d_out, int out_size) {
    const float* node_feat = (const float*)d_in[0];
    const int*   sizes     = (const int*)d_in[1];
    const float* query     = (const float*)d_in[2];
    const float* Wq        = (const float*)d_in[3];
    const float* bq        = (const float*)d_in[4];
    const float* Wk        = (const float*)d_in[5];
    /* bk = d_in[6] cancels in softmax */
    const float* Wv        = (const float*)d_in[7];
    const float* bv        = (const float*)d_in[8];
    const float* Wo        = (const float*)d_in[9];
    const float* bo        = (const float*)d_in[10];
    const float* Wp        = (const float*)d_in[11];
    const float* bp        = (const float*)d_in[12];
    float* out = (float*)d_out;

    float *pWc, *pcb, *paccx, *ppooled;
    cudaGetSymbolAddress((void**)&pWc, g_Wc);
    cudaGetSymbolAddress((void**)&pcb, g_cb);
    cudaGetSymbolAddress((void**)&paccx, g_accx);
    cudaGetSymbolAddress((void**)&ppooled, g_pooled);

    cudaFuncSetAttribute(attn2_kernel,
                         cudaFuncAttributeMaxDynamicSharedMemorySize, SMEM_X);

    cudaMemsetAsync(paccx, 0, (size_t)GDIM * HE * sizeof(float));

    // prep: wkq + scan + cb in one launch
    prep_kernel<<<HNUM + 1 + 22, EDIM>>>(Wq, query, bq, Wk, sizes, Wp, bo, bp);

    // Wc = Wp @ Wo   [256,384]
    gemm_s<false, false><<<dim3(EDIM / 32, OUTD / 64, 1), 128>>>(
        Wp, EDIM, Wo, EDIM, pWc, EDIM, nullptr, OUTD, EDIM, EDIM, 0, 0, 0, 0);

    // fused attention (single pass over node_feat) + normalize
    attn2_kernel<<<NUNITS, 256, SMEM_X>>>(node_feat, sizes);
    norm_kernel<<<GDIM, EDIM>>>(sizes);

    // pooled[g, h*64+d] = bv + Wv_h . accx_h   (batched over h)
    gemm_s<true, true><<<dim3(DHH / 32, GDIM / 64, HNUM), 128>>>(
        paccx, HE, Wv, EDIM, ppooled, EDIM, bv,
        GDIM, DHH, EDIM, /*zA=*/EDIM, /*zB=*/DHH * EDIM, /*zC=*/DHH, /*zBias=*/DHH);

    // out = pooled @ Wc^T + cb   [256,256]
    gemm_s<true, true><<<dim3(OUTD / 32, GDIM / 64, 1), 128>>>(
        ppooled, EDIM, pWc, EDIM, out, OUTD, pcb,
        GDIM, OUTD, EDIM, 0, 0, 0, 0);
}